// round 8
// baseline (speedup 1.0000x reference)
#include <cuda_runtime.h>

#define NN 50000
#define EE 500000
#define NB 8
#define NPGX 6250
#define FDIM 266   // 10 + 4*64
#define OUTC 532

// ---------------- scratch (device globals: no runtime allocation allowed) ----------------
__device__ float    g_F[(size_t)NN * FDIM];   // concat features
__device__ float    g_H[(size_t)NN * 64];     // current h
__device__ float    g_T[(size_t)NN * 128];    // MLP hidden
__device__ float    g_NP[(size_t)NN * 384];   // [ni | nj | nproj]
__device__ float    g_hatt[(size_t)NN * 128];
__device__ float    g_e[(size_t)EE * 2];      // logits, then exp()
__device__ unsigned g_m[NN * 2];              // mono-encoded segment max
__device__ float    g_s[NN * 2];              // softmax denom
__device__ float    g_gmax[NB * FDIM];
__device__ float    g_TeP[3][7 * 128];        // etype table (+ (rc_b+rp_b)@Wf + egat_bias)
__device__ float    g_Tr[3][31 * 128];
__device__ float    g_Arc[3][2 * 128];
__device__ float    g_Arp[3][3 * 128];

// ---------------- helpers ----------------
__device__ __forceinline__ void ffma2(unsigned long long& d, unsigned long long a, unsigned long long b) {
    asm("fma.rn.f32x2 %0, %1, %2, %0;" : "+l"(d) : "l"(a), "l"(b));
}
__device__ __forceinline__ unsigned long long dup2(float x) {
    unsigned long long r; asm("mov.b64 %0, {%1, %1};" : "=l"(r) : "f"(x)); return r;
}
__device__ __forceinline__ float2 unpk(unsigned long long v) {
    float2 r; asm("mov.b64 {%0, %1}, %2;" : "=f"(r.x), "=f"(r.y) : "l"(v)); return r;
}
__device__ __forceinline__ void red_add_v4(float* p, float a, float b, float c, float d) {
    asm volatile("red.global.add.v4.f32 [%0], {%1,%2,%3,%4};"
                 :: "l"(p), "f"(a), "f"(b), "f"(c), "f"(d) : "memory");
}
__device__ __forceinline__ unsigned mono(float f) {
    unsigned u = __float_as_uint(f);
    return u ^ (((unsigned)((int)u >> 31)) | 0x80000000u);
}
__device__ __forceinline__ float demono(unsigned u) {
    unsigned v = (u & 0x80000000u) ? (u ^ 0x80000000u) : ~u;
    return __uint_as_float(v);
}

// ---------------- zero per-layer scratch ----------------
__global__ void k_zero() {
    int i = blockIdx.x * blockDim.x + threadIdx.x;          // 1.6M threads
    ((float4*)g_hatt)[i] = make_float4(0.f, 0.f, 0.f, 0.f);
    if (i < (NN * 2) / 4) {
        ((uint4*)g_m)[i]  = make_uint4(0u, 0u, 0u, 0u);
        ((float4*)g_s)[i] = make_float4(0.f, 0.f, 0.f, 0.f);
    }
}

// ---------------- feature MLP: h0 = relu(feat@W0+b0)@W1+b1 ; writes F[:,0:74] ----------------
__global__ __launch_bounds__(128) void k_feat_mlp(const float* __restrict__ feat,
                                                  const float* __restrict__ W0, const float* __restrict__ b0,
                                                  const float* __restrict__ W1, const float* __restrict__ b1) {
    __shared__ float sW0[640], sb0[64], sW1[4096], sb1[64];
    int tid = threadIdx.x;
    for (int i = tid; i < 640;  i += 128) sW0[i] = W0[i];
    for (int i = tid; i < 4096; i += 128) sW1[i] = W1[i];
    if (tid < 64) { sb0[tid] = b0[tid]; sb1[tid] = b1[tid]; }
    __syncthreads();
    int row = blockIdx.x * 128 + tid;
    if (row >= NN) return;
    float x[10];
#pragma unroll
    for (int k = 0; k < 10; k++) x[k] = feat[(size_t)row * 10 + k];
#pragma unroll
    for (int k = 0; k < 10; k++) g_F[(size_t)row * FDIM + k] = x[k];
    float hid[64];
    for (int j = 0; j < 64; j++) {
        float a = sb0[j];
#pragma unroll
        for (int k = 0; k < 10; k++) a += x[k] * sW0[k * 64 + j];
        hid[j] = fmaxf(a, 0.f);
    }
    for (int j = 0; j < 64; j++) {
        float a = sb1[j];
#pragma unroll
        for (int k = 0; k < 64; k++) a += hid[k] * sW1[k * 64 + j];
        g_H[(size_t)row * 64 + j] = a;
        g_F[(size_t)row * FDIM + 10 + j] = a;
    }
}

// ---------------- per-layer edge tables: fold W_fij into tiny lookup tables ----------------
__global__ __launch_bounds__(256) void k_tables(const float* __restrict__ etype_emb, const float* __restrict__ rid_emb,
                                                const float* __restrict__ rc_W, const float* __restrict__ rc_b,
                                                const float* __restrict__ rp_W, const float* __restrict__ rp_b,
                                                const float* __restrict__ W_fij, const float* __restrict__ egat_bias) {
    int l = blockIdx.x;
    const float* Wf = W_fij + (size_t)l * 64 * 128;
    __shared__ float rows[43][64];
    __shared__ float cb[64];
    int tid = threadIdx.x;
    if (tid < 64) cb[tid] = rc_b[tid] + rp_b[tid];
    __syncthreads();
    for (int i = tid; i < 7 * 64;  i += 256) rows[i / 64][i % 64]      = etype_emb[i] + cb[i % 64];
    for (int i = tid; i < 31 * 64; i += 256) rows[7 + i / 64][i % 64]  = rid_emb[i];
    for (int i = tid; i < 2 * 64;  i += 256) rows[38 + i / 64][i % 64] = rc_W[i];
    for (int i = tid; i < 3 * 64;  i += 256) rows[40 + i / 64][i % 64] = rp_W[i];
    __syncthreads();
    for (int idx = tid; idx < 43 * 128; idx += 256) {
        int r = idx >> 7, o = idx & 127;
        float a = 0.f;
#pragma unroll
        for (int k = 0; k < 64; k++) a += rows[r][k] * Wf[k * 128 + o];
        if (r < 7)       g_TeP[l][r * 128 + o] = a + egat_bias[l * 128 + o];
        else if (r < 38) g_Tr[l][(r - 7) * 128 + o] = a;
        else if (r < 40) g_Arc[l][(r - 38) * 128 + o] = a;
        else             g_Arp[l][(r - 40) * 128 + o] = a;
    }
}

// ---------------- f32x2 GEMM: C[:,ccol:ccol+BN] = A(nrows x K) @ B(K x BN) (+bias)(relu)(+res)(->F) ----------------
template<int K, int BN>
__global__ __launch_bounds__(256) void k_gemm(const float* __restrict__ A, int lda,
                                              const float* __restrict__ B,
                                              const float* __restrict__ bias,
                                              float* C, int ldc, int ccol,
                                              int do_relu,
                                              const float* res,
                                              float* Fout, int fcol,
                                              int nrows) {
    constexpr int BM = 128, KC = 32, TN = BN / 16;
    __shared__ float As[KC][BM];
    __shared__ float Bs[KC][BN];
    int tid = threadIdx.x;
    int ty = tid >> 4, tx = tid & 15;
    int r0 = ty * 8, c0 = tx * TN;
    int rbase = blockIdx.x * BM;
    unsigned long long acc[8][TN / 2];
#pragma unroll
    for (int i = 0; i < 8; i++)
#pragma unroll
        for (int p = 0; p < TN / 2; p++) acc[i][p] = 0ull;

    for (int kk = 0; kk < K; kk += KC) {
#pragma unroll
        for (int i = 0; i < 4; i++) {                   // A: 128 rows x 32 k = 1024 float4
            int slot = tid + i * 256;
            int row = slot >> 3, q = slot & 7;
            float4 v = make_float4(0.f, 0.f, 0.f, 0.f);
            int gr = rbase + row;
            if (gr < nrows) v = *(const float4*)(A + (size_t)gr * lda + kk + q * 4);
            As[q * 4 + 0][row] = v.x; As[q * 4 + 1][row] = v.y;
            As[q * 4 + 2][row] = v.z; As[q * 4 + 3][row] = v.w;
        }
#pragma unroll
        for (int i = 0; i < (KC * BN / 4) / 256; i++) { // B tile
            int slot = tid + i * 256;
            int kr = slot / (BN / 4), q = slot % (BN / 4);
            *(float4*)&Bs[kr][q * 4] = *(const float4*)(B + (size_t)(kk + kr) * BN + q * 4);
        }
        __syncthreads();
#pragma unroll
        for (int k = 0; k < KC; k++) {
            float4 a0 = *(const float4*)&As[k][r0];
            float4 a1 = *(const float4*)&As[k][r0 + 4];
            unsigned long long aa[8];
            aa[0] = dup2(a0.x); aa[1] = dup2(a0.y); aa[2] = dup2(a0.z); aa[3] = dup2(a0.w);
            aa[4] = dup2(a1.x); aa[5] = dup2(a1.y); aa[6] = dup2(a1.z); aa[7] = dup2(a1.w);
            const unsigned long long* bp = (const unsigned long long*)&Bs[k][c0];
            unsigned long long bb[TN / 2];
#pragma unroll
            for (int p = 0; p < TN / 2; p++) bb[p] = bp[p];
#pragma unroll
            for (int i = 0; i < 8; i++)
#pragma unroll
                for (int p = 0; p < TN / 2; p++) ffma2(acc[i][p], aa[i], bb[p]);
        }
        __syncthreads();
    }
#pragma unroll
    for (int i = 0; i < 8; i++) {
        int gr = rbase + r0 + i;
        if (gr >= nrows) continue;
#pragma unroll
        for (int p = 0; p < TN / 2; p++) {
            float2 v = unpk(acc[i][p]);
            int j = c0 + p * 2;
            if (bias) { v.x += bias[j]; v.y += bias[j + 1]; }
            if (do_relu) { v.x = fmaxf(v.x, 0.f); v.y = fmaxf(v.y, 0.f); }
            if (res) { float2 rv = *(const float2*)(res + (size_t)gr * 64 + j); v.x += rv.x; v.y += rv.y; }
            *(float2*)(C + (size_t)gr * ldc + ccol + j) = v;
            if (Fout) *(float2*)(Fout + (size_t)gr * FDIM + fcol + j) = v;
        }
    }
}

// ---------------- attention logits + segment max (one warp per edge) ----------------
__global__ __launch_bounds__(256) void k_attn(int l,
                                              const int* __restrict__ src, const int* __restrict__ dst,
                                              const int* __restrict__ etype, const int* __restrict__ rid,
                                              const float* __restrict__ att_rc, const float* __restrict__ att_rp,
                                              const float* __restrict__ attnv) {
    int lane = threadIdx.x & 31;
    int gw = (blockIdx.x * blockDim.x + threadIdx.x) >> 5;
    int nw = (gridDim.x * blockDim.x) >> 5;
    int c = lane * 4;
    const float* Arc = g_Arc[l]; const float* Arp = g_Arp[l];
    const float* TeP = g_TeP[l]; const float* Trt = g_Tr[l];
    float4 arc0 = *(const float4*)(Arc + c);
    float4 arc1 = *(const float4*)(Arc + 128 + c);
    float4 arp0 = *(const float4*)(Arp + c);
    float4 arp1 = *(const float4*)(Arp + 128 + c);
    float4 arp2 = *(const float4*)(Arp + 256 + c);
    float4 at   = *(const float4*)(attnv + c);
    for (int e = gw; e < EE; e += nw) {
        int s  = __ldg(src + e),   d  = __ldg(dst + e);
        int et = __ldg(etype + e), rr = __ldg(rid + e);
        float2 rc = __ldg((const float2*)att_rc + e);
        const float* rpp = att_rp + (size_t)e * 3;
        float rp0 = __ldg(rpp), rp1 = __ldg(rpp + 1), rp2 = __ldg(rpp + 2);
        float4 te = *(const float4*)(TeP + et * 128 + c);
        float4 tr = *(const float4*)(Trt + rr * 128 + c);
        float4 ni = *(const float4*)(g_NP + (size_t)s * 384 + c);
        float4 nj = *(const float4*)(g_NP + (size_t)d * 384 + 128 + c);
        float fx = ni.x + nj.x + te.x + tr.x + rc.x * arc0.x + rc.y * arc1.x + rp0 * arp0.x + rp1 * arp1.x + rp2 * arp2.x;
        float fy = ni.y + nj.y + te.y + tr.y + rc.x * arc0.y + rc.y * arc1.y + rp0 * arp0.y + rp1 * arp1.y + rp2 * arp2.y;
        float fz = ni.z + nj.z + te.z + tr.z + rc.x * arc0.z + rc.y * arc1.z + rp0 * arp0.z + rp1 * arp1.z + rp2 * arp2.z;
        float fw = ni.w + nj.w + te.w + tr.w + rc.x * arc0.w + rc.y * arc1.w + rp0 * arp0.w + rp1 * arp1.w + rp2 * arp2.w;
        float p;
        p  = (fx > 0.f ? fx : 0.2f * fx) * at.x;
        p += (fy > 0.f ? fy : 0.2f * fy) * at.y;
        p += (fz > 0.f ? fz : 0.2f * fz) * at.z;
        p += (fw > 0.f ? fw : 0.2f * fw) * at.w;
        p += __shfl_xor_sync(0xffffffffu, p, 1);
        p += __shfl_xor_sync(0xffffffffu, p, 2);
        p += __shfl_xor_sync(0xffffffffu, p, 4);
        p += __shfl_xor_sync(0xffffffffu, p, 8);
        if ((lane & 15) == 0) {
            int h = lane >> 4;
            g_e[(size_t)e * 2 + h] = p;
            atomicMax(&g_m[(size_t)d * 2 + h], mono(p));
        }
    }
}

// ---------------- exp + segment sum ----------------
__global__ __launch_bounds__(256) void k_expsum(const int* __restrict__ dst) {
    int e = blockIdx.x * blockDim.x + threadIdx.x;
    if (e >= EE) return;
    int d = __ldg(dst + e);
    float2 ev = ((const float2*)g_e)[e];
    float m0 = demono(g_m[(size_t)d * 2]);
    float m1 = demono(g_m[(size_t)d * 2 + 1]);
    float x0 = __expf(ev.x - m0), x1 = __expf(ev.y - m1);
    ((float2*)g_e)[e] = make_float2(x0, x1);
    atomicAdd(&g_s[(size_t)d * 2], x0);
    atomicAdd(&g_s[(size_t)d * 2 + 1], x1);
}

// ---------------- message passing: h_att[dst] += alpha * nproj[src] (one warp per edge) ----------------
__global__ __launch_bounds__(256) void k_msg(const int* __restrict__ src, const int* __restrict__ dst) {
    int lane = threadIdx.x & 31;
    int gw = (blockIdx.x * blockDim.x + threadIdx.x) >> 5;
    int nw = (gridDim.x * blockDim.x) >> 5;
    int c = lane * 4;
    for (int e = gw; e < EE; e += nw) {
        int s = __ldg(src + e), d = __ldg(dst + e);
        float2 ex = __ldg((const float2*)g_e + e);
        float2 ss = __ldg((const float2*)g_s + d);
        float a0 = __fdividef(ex.x, ss.x + 1e-9f);
        float a1 = __fdividef(ex.y, ss.y + 1e-9f);
        float a = (lane < 16) ? a0 : a1;
        float4 np = *(const float4*)(g_NP + (size_t)s * 384 + 256 + c);
        red_add_v4(g_hatt + (size_t)d * 128 + c, a * np.x, a * np.y, a * np.z, a * np.w);
    }
}

// ---------------- graph max pooling ----------------
__global__ __launch_bounds__(256) void k_pool() {
    int chunk = blockIdx.x;            // 0..4 (64 cols each)
    int g = blockIdx.y;                // 0..7
    int tx = threadIdx.x & 63;
    int ty = threadIdx.x >> 6;         // 0..3
    int col = chunk * 64 + tx;
    float v = -3.4e38f;
    if (col < FDIM) {
        const float* base = g_F + (size_t)g * NPGX * FDIM + col;
        for (int r = ty; r < NPGX; r += 4) v = fmaxf(v, base[(size_t)r * FDIM]);
    }
    __shared__ float red[4][64];
    red[ty][tx] = v;
    __syncthreads();
    if (ty == 0 && col < FDIM) {
        v = fmaxf(fmaxf(red[0][tx], red[1][tx]), fmaxf(red[2][tx], red[3][tx]));
        g_gmax[g * FDIM + col] = v;
    }
}

// ---------------- output assembly: [features | graph_rep] ----------------
__global__ __launch_bounds__(256) void k_out(float2* __restrict__ out) {
    int idx = blockIdx.x * blockDim.x + threadIdx.x;        // float2 index
    const int TOT = NN * (OUTC / 2);                        // 13,300,000
    if (idx >= TOT) return;
    int c2 = idx % (OUTC / 2);
    int rn = idx / (OUTC / 2);
    int g = rn / NPGX;
    float2 v = (c2 < FDIM / 2) ? ((const float2*)g_F)[(size_t)rn * (FDIM / 2) + c2]
                               : ((const float2*)g_gmax)[(size_t)g * (FDIM / 2) + (c2 - FDIM / 2)];
    out[idx] = v;
}

// ---------------- host ----------------
extern "C" void kernel_launch(void* const* d_in, const int* in_sizes, int n_in,
                              void* d_out, int out_size) {
    (void)in_sizes; (void)n_in; (void)out_size;
    const float* feat      = (const float*)d_in[0];
    const float* att_rc    = (const float*)d_in[1];
    const float* att_rp    = (const float*)d_in[2];
    const float* etype_emb = (const float*)d_in[3];
    const float* rid_emb   = (const float*)d_in[4];
    const float* rc_W      = (const float*)d_in[5];
    const float* rc_b      = (const float*)d_in[6];
    const float* rp_W      = (const float*)d_in[7];
    const float* rp_b      = (const float*)d_in[8];
    const float* fe_W0     = (const float*)d_in[9];
    const float* fe_b0     = (const float*)d_in[10];
    const float* fe_W1     = (const float*)d_in[11];
    const float* fe_b1     = (const float*)d_in[12];
    const float* W_ni      = (const float*)d_in[13];
    const float* W_nj      = (const float*)d_in[14];
    const float* W_fij     = (const float*)d_in[15];
    const float* W_node    = (const float*)d_in[16];
    const float* attn      = (const float*)d_in[17];
    const float* egat_bias = (const float*)d_in[18];
    const float* Wm0       = (const float*)d_in[19];
    const float* bm0       = (const float*)d_in[20];
    const float* Wm1       = (const float*)d_in[21];
    const float* bm1       = (const float*)d_in[22];
    const int*   src       = (const int*)d_in[23];
    const int*   dst       = (const int*)d_in[24];
    const int*   etype     = (const int*)d_in[25];
    const int*   rid       = (const int*)d_in[26];

    float *pH, *pT, *pNP, *phatt, *pF;
    cudaGetSymbolAddress((void**)&pH,    g_H);
    cudaGetSymbolAddress((void**)&pT,    g_T);
    cudaGetSymbolAddress((void**)&pNP,   g_NP);
    cudaGetSymbolAddress((void**)&phatt, g_hatt);
    cudaGetSymbolAddress((void**)&pF,    g_F);

    const int GB = (NN + 127) / 128;   // 391 blocks of 128 rows

    k_feat_mlp<<<GB, 128>>>(feat, fe_W0, fe_b0, fe_W1, fe_b1);
    k_tables<<<3, 256>>>(etype_emb, rid_emb, rc_W, rc_b, rp_W, rp_b, W_fij, egat_bias);

    for (int l = 0; l < 3; l++) {
        k_zero<<<(NN * 128 / 4) / 256, 256>>>();
        k_gemm<64, 128><<<GB, 256>>>(pH, 64, W_ni + (size_t)l * 64 * 128, nullptr,
                                     pNP, 384, 0, 0, nullptr, nullptr, 0, NN);
        k_gemm<64, 128><<<GB, 256>>>(pH, 64, W_nj + (size_t)l * 64 * 128, nullptr,
                                     pNP, 384, 128, 0, nullptr, nullptr, 0, NN);
        k_gemm<64, 128><<<GB, 256>>>(pH, 64, W_node + (size_t)l * 64 * 128, nullptr,
                                     pNP, 384, 256, 0, nullptr, nullptr, 0, NN);
        k_attn<<<1184, 256>>>(l, src, dst, etype, rid, att_rc, att_rp, attn + (size_t)l * 128);
        k_expsum<<<(EE + 255) / 256, 256>>>(dst);
        k_msg<<<1184, 256>>>(src, dst);
        k_gemm<128, 128><<<GB, 256>>>(phatt, 128, Wm0 + (size_t)l * 128 * 128, bm0 + (size_t)l * 128,
                                      pT, 128, 0, 1, nullptr, nullptr, 0, NN);
        k_gemm<128, 64><<<GB, 256>>>(pT, 128, Wm1 + (size_t)l * 128 * 64, bm1 + (size_t)l * 64,
                                     pH, 64, 0, 0, pH, pF, 10 + 64 * (l + 1), NN);
    }
    k_pool<<<dim3(5, NB), 256>>>();
    k_out<<<(NN * (OUTC / 2) + 255) / 256, 256>>>((float2*)d_out);
}